// round 3
// baseline (speedup 1.0000x reference)
#include <cuda_runtime.h>
#include <math.h>

#define B_  4
#define S_  2048
#define D_  1024
#define H_  16
#define DK_ 64
#define M_  (B_ * S_)

// Scratch (device globals: no allocations allowed in kernel_launch)
__device__ float g_Q[(size_t)B_ * H_ * S_ * DK_];   // [b,h,s,dk]
__device__ float g_K[(size_t)B_ * H_ * S_ * DK_];
__device__ float g_V[(size_t)B_ * H_ * S_ * DK_];
__device__ float g_O[(size_t)B_ * S_ * D_];         // [b,s,h*dk]
__device__ float g_cos[S_ * 32];
__device__ float g_sin[S_ * 32];

// ---------------------------------------------------------------------------
// RoPE table: match reference fp32 pipeline (inv_freq fp32, angle fp32), then
// take sin/cos in double so fast-math cannot wreck large-angle reduction.
// ---------------------------------------------------------------------------
__global__ void rope_table_kernel(const int* __restrict__ pos) {
    int idx = blockIdx.x * blockDim.x + threadIdx.x;
    if (idx >= S_ * 32) return;
    int s = idx >> 5;
    int p = idx & 31;
    float inv_freq = (float)pow(10000.0, -((double)(2 * p)) / 64.0);
    float ang = (float)pos[s] * inv_freq;   // fp32 angle, like the reference
    g_cos[idx] = (float)cos((double)ang);
    g_sin[idx] = (float)sin((double)ang);
}

// ---------------------------------------------------------------------------
// GEMM NT: C[M,N] = A[M,K] * W[N,K]^T   (M=8192, N=K=1024 fixed)
// 128x128 CTA tile, BK=16, 256 threads, 8x8 per-thread micro-tile.
// SRC  0: A = Ain argument (harness pointer)
//      1: A = g_O (device global — must be resolved in DEVICE code, never
//         passed from host: the host-side symbol is an ATS-readable host
//         shadow full of zeros, which is what broke rounds 1-2)
// MODE 0: plain row-major store to Cout
// MODE 1: RoPE epilogue, scatter to [b,h,s,dk] (DST selects g_Q/g_K)
// MODE 2: no RoPE, scatter to [b,h,s,dk] (g_V)
// DST  0/1/2: g_Q/g_K/g_V, 3: Cout argument
// ---------------------------------------------------------------------------
template <int MODE, int DST, int SRC>
__global__ void __launch_bounds__(256) gemm_nt_kernel(
    const float* __restrict__ Ain, const float* __restrict__ W,
    float* __restrict__ Cout)
{
    const int K = D_;
    const int N = D_;
    __shared__ __align__(16) float As[16][128];
    __shared__ __align__(16) float Bs[16][128];

    const float* A = (SRC == 0) ? Ain : (const float*)g_O;

    const int tid = threadIdx.x;
    const int tm = tid >> 4;      // 0..15
    const int tn = tid & 15;      // 0..15
    const int m0 = blockIdx.y * 128;
    const int n0 = blockIdx.x * 128;

    float acc[8][8];
#pragma unroll
    for (int i = 0; i < 8; ++i)
#pragma unroll
        for (int j = 0; j < 8; ++j) acc[i][j] = 0.f;

    for (int kt = 0; kt < K; kt += 16) {
#pragma unroll
        for (int u = 0; u < 2; ++u) {
            int f = tid + u * 256;          // 0..511
            int r = f >> 2;                 // 0..127
            int k4 = (f & 3) << 2;          // 0,4,8,12
            float4 va = *(const float4*)(A + (size_t)(m0 + r) * K + kt + k4);
            As[k4 + 0][r] = va.x; As[k4 + 1][r] = va.y;
            As[k4 + 2][r] = va.z; As[k4 + 3][r] = va.w;
            float4 vb = *(const float4*)(W + (size_t)(n0 + r) * K + kt + k4);
            Bs[k4 + 0][r] = vb.x; Bs[k4 + 1][r] = vb.y;
            Bs[k4 + 2][r] = vb.z; Bs[k4 + 3][r] = vb.w;
        }
        __syncthreads();
#pragma unroll
        for (int kk = 0; kk < 16; ++kk) {
            float4 a0 = *(const float4*)&As[kk][tm * 8];
            float4 a1 = *(const float4*)&As[kk][tm * 8 + 4];
            float4 b0 = *(const float4*)&Bs[kk][tn * 8];
            float4 b1 = *(const float4*)&Bs[kk][tn * 8 + 4];
            float a[8] = {a0.x, a0.y, a0.z, a0.w, a1.x, a1.y, a1.z, a1.w};
            float b[8] = {b0.x, b0.y, b0.z, b0.w, b1.x, b1.y, b1.z, b1.w};
#pragma unroll
            for (int i = 0; i < 8; ++i)
#pragma unroll
                for (int j = 0; j < 8; ++j)
                    acc[i][j] += a[i] * b[j];
        }
        __syncthreads();
    }

    float* C;
    if (DST == 0)      C = g_Q;
    else if (DST == 1) C = g_K;
    else if (DST == 2) C = g_V;
    else               C = Cout;

    if (MODE == 0) {
#pragma unroll
        for (int i = 0; i < 8; ++i) {
            int row = m0 + tm * 8 + i;
            float* dst = C + (size_t)row * N + n0 + tn * 8;
            *(float4*)dst = make_float4(acc[i][0], acc[i][1], acc[i][2], acc[i][3]);
            *(float4*)(dst + 4) = make_float4(acc[i][4], acc[i][5], acc[i][6], acc[i][7]);
        }
    } else {
        const int n_base = n0 + tn * 8;     // 8-aligned => never crosses a head
        const int h = n_base >> 6;
        const int jj0 = n_base & 63;
#pragma unroll
        for (int i = 0; i < 8; ++i) {
            int m = m0 + tm * 8 + i;
            int b = m >> 11;                // /S_ (S_=2048)
            int s = m & (S_ - 1);
            float out[8];
#pragma unroll
            for (int j = 0; j < 8; j += 2) {
                float x0 = acc[i][j], x1 = acc[i][j + 1];
                if (MODE == 1) {
                    int p = (jj0 + j) >> 1;
                    float c = g_cos[s * 32 + p];
                    float sn = g_sin[s * 32 + p];
                    out[j]     = c * x0 - sn * x1;
                    out[j + 1] = sn * x0 + c * x1;
                } else {
                    out[j] = x0; out[j + 1] = x1;
                }
            }
            float* dst = C + (((size_t)(b * H_ + h) * S_ + s) * DK_ + jj0);
            *(float4*)dst       = make_float4(out[0], out[1], out[2], out[3]);
            *(float4*)(dst + 4) = make_float4(out[4], out[5], out[6], out[7]);
        }
    }
}

// ---------------------------------------------------------------------------
// Flash attention (causal). One CTA = 64 queries of one (b,h).
// 256 threads = 16x16. BQ=64, BK=32. STATIC shared memory (41.5 KB < 48 KB).
//   Qs[64][64]  16 KB   (pre-scaled by 1/8)
//   Ks[32][68]   8.5 KB (padded stride)
//   Vs[32][64]   8 KB
//   Ps[64][32]   8 KB
// Per-thread: S micro-tile 4x2, O micro-tile 4x4.
// ---------------------------------------------------------------------------
__global__ void __launch_bounds__(256) attn_kernel() {
    __shared__ __align__(16) float Qs[64 * 64];
    __shared__ __align__(16) float Ks[32 * 68];
    __shared__ __align__(16) float Vs[32 * 64];
    __shared__ __align__(16) float Ps[64 * 32];

    const int qb = gridDim.x - 1 - blockIdx.x;   // heavy tiles first
    const int bh = blockIdx.y;
    const int b = bh >> 4;
    const int h = bh & 15;
    const int tid = threadIdx.x;
    const int ty = tid >> 4;           // 0..15  -> query rows ty*4..ty*4+3
    const int tx = tid & 15;           // 0..15

    const size_t headbase = (size_t)bh * S_ * DK_;

    // Load Q tile, pre-scaled by 1/sqrt(64)
#pragma unroll
    for (int u = 0; u < 4; ++u) {
        int f = tid + u * 256;                 // 0..1023
        int r = f >> 4;
        int c4 = (f & 15) << 2;
        float4 v = *(const float4*)(g_Q + headbase + (size_t)(qb * 64 + r) * 64 + c4);
        *(float4*)&Qs[r * 64 + c4] =
            make_float4(v.x * 0.125f, v.y * 0.125f, v.z * 0.125f, v.w * 0.125f);
    }

    float Oa[4][4];
    float mrow[4], lrow[4];
#pragma unroll
    for (int i = 0; i < 4; ++i) {
        mrow[i] = -3.0e38f;
        lrow[i] = 0.f;
#pragma unroll
        for (int j = 0; j < 4; ++j) Oa[i][j] = 0.f;
    }

    const int nkb = 2 * qb + 2;        // 32-wide key blocks covering [0, qb*64+64)
    for (int kb = 0; kb < nkb; ++kb) {
        __syncthreads();   // previous PV reads done before overwriting K/V
        {
            // 32x64 tile = 512 float4s, 256 threads -> 2 each
#pragma unroll
            for (int u = 0; u < 2; ++u) {
                int f = tid + u * 256;         // 0..511
                int r = f >> 4;                // 0..31
                int c4 = (f & 15) << 2;        // 0..60
                float4 kv = *(const float4*)(g_K + headbase + (size_t)(kb * 32 + r) * 64 + c4);
                *(float4*)&Ks[r * 68 + c4] = kv;
                float4 vv = *(const float4*)(g_V + headbase + (size_t)(kb * 32 + r) * 64 + c4);
                *(float4*)&Vs[r * 64 + c4] = vv;
            }
        }
        __syncthreads();

        // S = Q * K^T (pre-scaled): 4 rows x 2 cols per thread
        float sacc[4][2];
#pragma unroll
        for (int i = 0; i < 4; ++i) { sacc[i][0] = 0.f; sacc[i][1] = 0.f; }

#pragma unroll
        for (int dc = 0; dc < 16; ++dc) {
            float4 qf[4], kf[2];
#pragma unroll
            for (int i = 0; i < 4; ++i)
                qf[i] = *(const float4*)&Qs[(ty * 4 + i) * 64 + dc * 4];
#pragma unroll
            for (int j = 0; j < 2; ++j)
                kf[j] = *(const float4*)&Ks[(tx * 2 + j) * 68 + dc * 4];
#pragma unroll
            for (int i = 0; i < 4; ++i)
#pragma unroll
                for (int j = 0; j < 2; ++j)
                    sacc[i][j] += qf[i].x * kf[j].x + qf[i].y * kf[j].y +
                                  qf[i].z * kf[j].z + qf[i].w * kf[j].w;
        }

        if (kb >= 2 * qb) {   // causal mask possible only in last two blocks
#pragma unroll
            for (int i = 0; i < 4; ++i)
#pragma unroll
                for (int j = 0; j < 2; ++j)
                    if (kb * 32 + tx * 2 + j > qb * 64 + ty * 4 + i)
                        sacc[i][j] = -3.0e38f;
        }

        // Online softmax (row = 16 lanes sharing the same ty)
#pragma unroll
        for (int i = 0; i < 4; ++i) {
            float mx = fmaxf(sacc[i][0], sacc[i][1]);
            mx = fmaxf(mx, __shfl_xor_sync(0xffffffffu, mx, 1));
            mx = fmaxf(mx, __shfl_xor_sync(0xffffffffu, mx, 2));
            mx = fmaxf(mx, __shfl_xor_sync(0xffffffffu, mx, 4));
            mx = fmaxf(mx, __shfl_xor_sync(0xffffffffu, mx, 8));
            float mnew = fmaxf(mrow[i], mx);
            float alpha = __expf(mrow[i] - mnew);
            float rs = 0.f;
#pragma unroll
            for (int j = 0; j < 2; ++j) {
                float p = __expf(sacc[i][j] - mnew);
                Ps[(ty * 4 + i) * 32 + tx * 2 + j] = p;
                rs += p;
            }
            rs += __shfl_xor_sync(0xffffffffu, rs, 1);
            rs += __shfl_xor_sync(0xffffffffu, rs, 2);
            rs += __shfl_xor_sync(0xffffffffu, rs, 4);
            rs += __shfl_xor_sync(0xffffffffu, rs, 8);
            lrow[i] = lrow[i] * alpha + rs;
            mrow[i] = mnew;
#pragma unroll
            for (int j = 0; j < 4; ++j) Oa[i][j] *= alpha;
        }
        __syncthreads();

        // O += P * V   (P: 64x32, V: 32x64)
#pragma unroll
        for (int kc = 0; kc < 8; ++kc) {
            float4 pf[4], vf[4];
#pragma unroll
            for (int i = 0; i < 4; ++i)
                pf[i] = *(const float4*)&Ps[(ty * 4 + i) * 32 + kc * 4];
#pragma unroll
            for (int l = 0; l < 4; ++l)
                vf[l] = *(const float4*)&Vs[(kc * 4 + l) * 64 + tx * 4];
#pragma unroll
            for (int i = 0; i < 4; ++i) {
                Oa[i][0] += pf[i].x * vf[0].x + pf[i].y * vf[1].x +
                            pf[i].z * vf[2].x + pf[i].w * vf[3].x;
                Oa[i][1] += pf[i].x * vf[0].y + pf[i].y * vf[1].y +
                            pf[i].z * vf[2].y + pf[i].w * vf[3].y;
                Oa[i][2] += pf[i].x * vf[0].z + pf[i].y * vf[1].z +
                            pf[i].z * vf[2].z + pf[i].w * vf[3].z;
                Oa[i][3] += pf[i].x * vf[0].w + pf[i].y * vf[1].w +
                            pf[i].z * vf[2].w + pf[i].w * vf[3].w;
            }
        }
    }

    // Normalize and write O in [b, s, h, dk] layout (= [b,s,D] row-major)
#pragma unroll
    for (int i = 0; i < 4; ++i) {
        float inv = 1.0f / lrow[i];
        int s = qb * 64 + ty * 4 + i;
        size_t idx = ((size_t)(b * S_ + s) * H_ + h) * DK_ + tx * 4;
        *(float4*)(g_O + idx) = make_float4(Oa[i][0] * inv, Oa[i][1] * inv,
                                            Oa[i][2] * inv, Oa[i][3] * inv);
    }
}

// ---------------------------------------------------------------------------
// Launch
// ---------------------------------------------------------------------------
extern "C" void kernel_launch(void* const* d_in, const int* in_sizes, int n_in,
                              void* d_out, int out_size) {
    const float* x   = (const float*)d_in[0];
    const int*   pos = (const int*)d_in[1];
    const float* wq  = (const float*)d_in[2];
    const float* wk  = (const float*)d_in[3];
    const float* wv  = (const float*)d_in[4];
    const float* wo  = (const float*)d_in[5];
    float* out = (float*)d_out;

    (void)in_sizes; (void)n_in; (void)out_size;

    // 1. RoPE tables
    rope_table_kernel<<<(S_ * 32 + 255) / 256, 256>>>(pos);

    // 2. QKV projections (fused RoPE + [b,h,s,dk] scatter)
    dim3 ggrid(D_ / 128, M_ / 128);
    gemm_nt_kernel<1, 0, 0><<<ggrid, 256>>>(x, wq, nullptr);
    gemm_nt_kernel<1, 1, 0><<<ggrid, 256>>>(x, wk, nullptr);
    gemm_nt_kernel<2, 2, 0><<<ggrid, 256>>>(x, wv, nullptr);

    // 3. Causal flash attention (static smem)
    attn_kernel<<<dim3(S_ / 64, B_ * H_), 256>>>();

    // 4. Output projection -> d_out (A = g_O selected in device code via SRC=1)
    gemm_nt_kernel<0, 3, 1><<<ggrid, 256>>>(nullptr, wo, out);
}

// round 5
// speedup vs baseline: 1.5542x; 1.5542x over previous
#include <cuda_runtime.h>
#include <cuda_bf16.h>
#include <math.h>
#include <stdint.h>

#define B_  4
#define S_  2048
#define D_  1024
#define H_  16
#define DK_ 64
#define M_  (B_ * S_)

// ---------------------------------------------------------------------------
// Device-global scratch (no allocations allowed)
// ---------------------------------------------------------------------------
__device__ float g_Q[(size_t)B_ * H_ * S_ * DK_];   // [b,h,s,dk]
__device__ float g_K[(size_t)B_ * H_ * S_ * DK_];
__device__ float g_V[(size_t)B_ * H_ * S_ * DK_];
__device__ float g_O[(size_t)B_ * S_ * D_];         // [b,s,h*dk]
__device__ float g_cos[S_ * 32];
__device__ float g_sin[S_ * 32];

// bf16 hi/lo split operands for tensor-core GEMMs
__device__ __nv_bfloat16 g_xhi[(size_t)M_ * D_];
__device__ __nv_bfloat16 g_xlo[(size_t)M_ * D_];
__device__ __nv_bfloat16 g_whi[4][(size_t)D_ * D_];   // q,k,v,o
__device__ __nv_bfloat16 g_wlo[4][(size_t)D_ * D_];
__device__ __nv_bfloat16 g_ohi[(size_t)M_ * D_];
__device__ __nv_bfloat16 g_olo[(size_t)M_ * D_];

// ---------------------------------------------------------------------------
// Warp-level tensor core helpers (sm_80+ PTX — assembles for plain sm_103)
// ---------------------------------------------------------------------------
__device__ __forceinline__ uint32_t smem_u32(const void* p) {
    uint32_t a;
    asm("{ .reg .u64 t; cvta.to.shared.u64 t, %1; cvt.u32.u64 %0, t; }"
        : "=r"(a) : "l"(p));
    return a;
}

__device__ __forceinline__ void ldsm_x4(uint32_t* r, uint32_t addr) {
    asm volatile("ldmatrix.sync.aligned.m8n8.x4.shared.b16 {%0,%1,%2,%3}, [%4];"
                 : "=r"(r[0]), "=r"(r[1]), "=r"(r[2]), "=r"(r[3])
                 : "r"(addr));
}

__device__ __forceinline__ void mma_bf16(float* d, const uint32_t* a,
                                         const uint32_t* b) {
    asm volatile(
        "mma.sync.aligned.m16n8k16.row.col.f32.bf16.bf16.f32 "
        "{%0,%1,%2,%3}, {%4,%5,%6,%7}, {%8,%9}, {%0,%1,%2,%3};"
        : "+f"(d[0]), "+f"(d[1]), "+f"(d[2]), "+f"(d[3])
        : "r"(a[0]), "r"(a[1]), "r"(a[2]), "r"(a[3]), "r"(b[0]), "r"(b[1]));
}

// ---------------------------------------------------------------------------
// RoPE table
// ---------------------------------------------------------------------------
__global__ void rope_table_kernel(const int* __restrict__ pos) {
    int idx = blockIdx.x * blockDim.x + threadIdx.x;
    if (idx >= S_ * 32) return;
    int s = idx >> 5;
    int p = idx & 31;
    float inv_freq = (float)pow(10000.0, -((double)(2 * p)) / 64.0);
    float ang = (float)pos[s] * inv_freq;
    g_cos[idx] = (float)cos((double)ang);
    g_sin[idx] = (float)sin((double)ang);
}

// ---------------------------------------------------------------------------
// fp32 -> bf16 hi/lo split. IDX: 0=x, 1..4=w[q,k,v,o], 5=g_O (arg ignored)
// ---------------------------------------------------------------------------
template <int IDX>
__global__ void convert_split_kernel(const float* __restrict__ srcArg, int n4) {
    int i = blockIdx.x * blockDim.x + threadIdx.x;
    if (i >= n4) return;
    const float* src;
    __nv_bfloat16 *hi, *lo;
    if (IDX == 0)      { src = srcArg; hi = g_xhi;          lo = g_xlo; }
    else if (IDX <= 4) { src = srcArg; hi = g_whi[IDX - 1]; lo = g_wlo[IDX - 1]; }
    else               { src = g_O;    hi = g_ohi;          lo = g_olo; }

    float4 v = ((const float4*)src)[i];
    __nv_bfloat16 h0 = __float2bfloat16_rn(v.x);
    __nv_bfloat16 h1 = __float2bfloat16_rn(v.y);
    __nv_bfloat16 h2 = __float2bfloat16_rn(v.z);
    __nv_bfloat16 h3 = __float2bfloat16_rn(v.w);
    __nv_bfloat16 l0 = __float2bfloat16_rn(v.x - __bfloat162float(h0));
    __nv_bfloat16 l1 = __float2bfloat16_rn(v.y - __bfloat162float(h1));
    __nv_bfloat16 l2 = __float2bfloat16_rn(v.z - __bfloat162float(h2));
    __nv_bfloat16 l3 = __float2bfloat16_rn(v.w - __bfloat162float(h3));
    ((__nv_bfloat162*)hi)[2 * i]     = __halves2bfloat162(h0, h1);
    ((__nv_bfloat162*)hi)[2 * i + 1] = __halves2bfloat162(h2, h3);
    ((__nv_bfloat162*)lo)[2 * i]     = __halves2bfloat162(l0, l1);
    ((__nv_bfloat162*)lo)[2 * i + 1] = __halves2bfloat162(l2, l3);
}

// ---------------------------------------------------------------------------
// mma.sync bf16x3 GEMM: C[M,N] = A[M,1024] * W[N,1024]^T.
// CTA tile 128x128, BK=64, 8 warps (4x2), warp tile 32x64.
// smem: 4 tiles of 128 rows x 144 B (row pad => ldmatrix conflict-free).
// SRC: 0 -> A = x split, 1 -> A = O split. WSEL: weight index 0..3.
// MODE 0: row-major store to Cout; MODE 1: RoPE+scatter; MODE 2: scatter.
// DST: 0/1/2 -> g_Q/g_K/g_V, 3 -> Cout.
// ---------------------------------------------------------------------------
#define T_STRIDE 144                      // bytes per smem row (64 bf16 + pad)
#define T_BYTES  (128 * T_STRIDE)         // 18432 per tile
#define GEMM_SMEM (4 * T_BYTES)           // 73728

template <int MODE, int DST, int SRC, int WSEL>
__global__ void __launch_bounds__(256) mma_gemm_kernel(float* __restrict__ Cout) {
    extern __shared__ char sm[];
    const int tid  = threadIdx.x;
    const int w    = tid >> 5;
    const int lane = tid & 31;
    const int wm   = w >> 1;            // 0..3
    const int wn   = w & 1;             // 0..1
    const int n0   = blockIdx.x * 128;
    const int m0   = blockIdx.y * 128;

    const uint32_t sbase = smem_u32(sm);
    const uint32_t oA[2] = { 0u, (uint32_t)T_BYTES };              // Ahi, Alo
    const uint32_t oB[2] = { (uint32_t)(2 * T_BYTES), (uint32_t)(3 * T_BYTES) };

    const __nv_bfloat16* srcA[2] = {
        ((SRC == 0) ? g_xhi : g_ohi) + (size_t)m0 * D_,
        ((SRC == 0) ? g_xlo : g_olo) + (size_t)m0 * D_ };
    const __nv_bfloat16* srcB[2] = {
        g_whi[WSEL] + (size_t)n0 * D_,
        g_wlo[WSEL] + (size_t)n0 * D_ };

    float d[2][8][4];
#pragma unroll
    for (int i = 0; i < 2; ++i)
#pragma unroll
        for (int j = 0; j < 8; ++j)
#pragma unroll
            for (int q = 0; q < 4; ++q) d[i][j][q] = 0.f;

    for (int kt = 0; kt < 16; ++kt) {
        __syncthreads();   // previous compute done before overwrite
        // Load 4 tiles (Ahi, Alo, Bhi, Blo): each 128 rows x 8 uint4
#pragma unroll
        for (int t = 0; t < 4; ++t) {
            const __nv_bfloat16* src = (t < 2) ? srcA[t] : srcB[t - 2];
            uint32_t dstoff = (t < 2) ? oA[t] : oB[t - 2];
            char* dst = sm + dstoff;
#pragma unroll
            for (int u = 0; u < 4; ++u) {
                int f = tid + u * 256;          // 0..1023
                int r = f >> 3;                 // 0..127
                int c = f & 7;                  // 0..7
                uint4 v = *(const uint4*)(src + (size_t)r * D_ + kt * 64 + c * 8);
                *(uint4*)(dst + r * T_STRIDE + c * 16) = v;
            }
        }
        __syncthreads();

#pragma unroll
        for (int ks = 0; ks < 4; ++ks) {
            const int k0 = ks * 16;
            // A fragments: 2 m16-tiles x (hi, lo)
            uint32_t ah[2][4], al[2][4];
            {
                int arow = wm * 32 + (lane & 15);
                int acol = 2 * k0 + (lane >> 4) * 16;   // bytes
#pragma unroll
                for (int i = 0; i < 2; ++i) {
                    uint32_t off = (uint32_t)((arow + i * 16) * T_STRIDE + acol);
                    ldsm_x4(ah[i], sbase + oA[0] + off);
                    ldsm_x4(al[i], sbase + oA[1] + off);
                }
            }
            // B fragments: 8 n8-tiles x (hi, lo), loaded as 4 x4-groups each
            uint32_t bh[8][2], bl[8][2];
            {
                int brow_l = (lane & 7) + ((lane >> 4) & 1) * 8;
                int bcol   = 2 * k0 + ((lane >> 3) & 1) * 16;    // bytes
#pragma unroll
                for (int g = 0; g < 4; ++g) {
                    uint32_t off = (uint32_t)((wn * 64 + g * 16 + brow_l) * T_STRIDE + bcol);
                    uint32_t r4[4];
                    ldsm_x4(r4, sbase + oB[0] + off);
                    bh[2 * g][0] = r4[0]; bh[2 * g][1] = r4[1];
                    bh[2 * g + 1][0] = r4[2]; bh[2 * g + 1][1] = r4[3];
                    ldsm_x4(r4, sbase + oB[1] + off);
                    bl[2 * g][0] = r4[0]; bl[2 * g][1] = r4[1];
                    bl[2 * g + 1][0] = r4[2]; bl[2 * g + 1][1] = r4[3];
                }
            }
            // bf16x3: hi*hi + lo*hi + hi*lo
#pragma unroll
            for (int i = 0; i < 2; ++i)
#pragma unroll
                for (int j = 0; j < 8; ++j) {
                    mma_bf16(d[i][j], ah[i], bh[j]);
                    mma_bf16(d[i][j], al[i], bh[j]);
                    mma_bf16(d[i][j], ah[i], bl[j]);
                }
        }
    }

    // Epilogue. D-fragment: (d0,d1) at (row, 2c..2c+1), (d2,d3) at (row+8, same)
    float* C;
    if (DST == 0)      C = g_Q;
    else if (DST == 1) C = g_K;
    else if (DST == 2) C = g_V;
    else               C = Cout;

#pragma unroll
    for (int i = 0; i < 2; ++i) {
        int mrow = m0 + wm * 32 + i * 16 + (lane >> 2);
#pragma unroll
        for (int half = 0; half < 2; ++half) {
            int m = mrow + half * 8;
            int b = m >> 11;
            int s = m & (S_ - 1);
#pragma unroll
            for (int j = 0; j < 8; ++j) {
                int n = n0 + wn * 64 + j * 8 + 2 * (lane & 3);
                float x0 = d[i][j][2 * half];
                float x1 = d[i][j][2 * half + 1];
                if (MODE == 0) {
                    *(float2*)(C + (size_t)m * D_ + n) = make_float2(x0, x1);
                } else {
                    int h = n >> 6;
                    int dk = n & 63;
                    float y0, y1;
                    if (MODE == 1) {
                        int p = dk >> 1;
                        float c = g_cos[s * 32 + p];
                        float sn = g_sin[s * 32 + p];
                        y0 = c * x0 - sn * x1;
                        y1 = sn * x0 + c * x1;
                    } else {
                        y0 = x0; y1 = x1;
                    }
                    *(float2*)(C + (((size_t)(b * H_ + h) * S_ + s) * DK_ + dk)) =
                        make_float2(y0, y1);
                }
            }
        }
    }
}

// ---------------------------------------------------------------------------
// Flash attention (causal), unchanged from the passing round.
// ---------------------------------------------------------------------------
__global__ void __launch_bounds__(256) attn_kernel() {
    __shared__ __align__(16) float Qs[64 * 64];
    __shared__ __align__(16) float Ks[32 * 68];
    __shared__ __align__(16) float Vs[32 * 64];
    __shared__ __align__(16) float Ps[64 * 32];

    const int qb = gridDim.x - 1 - blockIdx.x;
    const int bh = blockIdx.y;
    const int b = bh >> 4;
    const int h = bh & 15;
    const int tid = threadIdx.x;
    const int ty = tid >> 4;
    const int tx = tid & 15;

    const size_t headbase = (size_t)bh * S_ * DK_;

#pragma unroll
    for (int u = 0; u < 4; ++u) {
        int f = tid + u * 256;
        int r = f >> 4;
        int c4 = (f & 15) << 2;
        float4 v = *(const float4*)(g_Q + headbase + (size_t)(qb * 64 + r) * 64 + c4);
        *(float4*)&Qs[r * 64 + c4] =
            make_float4(v.x * 0.125f, v.y * 0.125f, v.z * 0.125f, v.w * 0.125f);
    }

    float Oa[4][4];
    float mrow[4], lrow[4];
#pragma unroll
    for (int i = 0; i < 4; ++i) {
        mrow[i] = -3.0e38f;
        lrow[i] = 0.f;
#pragma unroll
        for (int j = 0; j < 4; ++j) Oa[i][j] = 0.f;
    }

    const int nkb = 2 * qb + 2;
    for (int kb = 0; kb < nkb; ++kb) {
        __syncthreads();
#pragma unroll
        for (int u = 0; u < 2; ++u) {
            int f = tid + u * 256;
            int r = f >> 4;
            int c4 = (f & 15) << 2;
            float4 kv = *(const float4*)(g_K + headbase + (size_t)(kb * 32 + r) * 64 + c4);
            *(float4*)&Ks[r * 68 + c4] = kv;
            float4 vv = *(const float4*)(g_V + headbase + (size_t)(kb * 32 + r) * 64 + c4);
            *(float4*)&Vs[r * 64 + c4] = vv;
        }
        __syncthreads();

        float sacc[4][2];
#pragma unroll
        for (int i = 0; i < 4; ++i) { sacc[i][0] = 0.f; sacc[i][1] = 0.f; }

#pragma unroll
        for (int dc = 0; dc < 16; ++dc) {
            float4 qf[4], kf[2];
#pragma unroll
            for (int i = 0; i < 4; ++i)
                qf[i] = *(const float4*)&Qs[(ty * 4 + i) * 64 + dc * 4];
#pragma unroll
            for (int j = 0; j < 2; ++j)
                kf[j] = *(const float4*)&Ks[(tx * 2 + j) * 68 + dc * 4];
#pragma unroll
            for (int i = 0; i < 4; ++i)
#pragma unroll
                for (int j = 0; j < 2; ++j)
                    sacc[i][j] += qf[i].x * kf[j].x + qf[i].y * kf[j].y +
                                  qf[i].z * kf[j].z + qf[i].w * kf[j].w;
        }

        if (kb >= 2 * qb) {
#pragma unroll
            for (int i = 0; i < 4; ++i)
#pragma unroll
                for (int j = 0; j < 2; ++j)
                    if (kb * 32 + tx * 2 + j > qb * 64 + ty * 4 + i)
                        sacc[i][j] = -3.0e38f;
        }

#pragma unroll
        for (int i = 0; i < 4; ++i) {
            float mx = fmaxf(sacc[i][0], sacc[i][1]);
            mx = fmaxf(mx, __shfl_xor_sync(0xffffffffu, mx, 1));
            mx = fmaxf(mx, __shfl_xor_sync(0xffffffffu, mx, 2));
            mx = fmaxf(mx, __shfl_xor_sync(0xffffffffu, mx, 4));
            mx = fmaxf(mx, __shfl_xor_sync(0xffffffffu, mx, 8));
            float mnew = fmaxf(mrow[i], mx);
            float alpha = __expf(mrow[i] - mnew);
            float rs = 0.f;
#pragma unroll
            for (int j = 0; j < 2; ++j) {
                float p = __expf(sacc[i][j] - mnew);
                Ps[(ty * 4 + i) * 32 + tx * 2 + j] = p;
                rs += p;
            }
            rs += __shfl_xor_sync(0xffffffffu, rs, 1);
            rs += __shfl_xor_sync(0xffffffffu, rs, 2);
            rs += __shfl_xor_sync(0xffffffffu, rs, 4);
            rs += __shfl_xor_sync(0xffffffffu, rs, 8);
            lrow[i] = lrow[i] * alpha + rs;
            mrow[i] = mnew;
#pragma unroll
            for (int j = 0; j < 4; ++j) Oa[i][j] *= alpha;
        }
        __syncthreads();

#pragma unroll
        for (int kc = 0; kc < 8; ++kc) {
            float4 pf[4], vf[4];
#pragma unroll
            for (int i = 0; i < 4; ++i)
                pf[i] = *(const float4*)&Ps[(ty * 4 + i) * 32 + kc * 4];
#pragma unroll
            for (int l = 0; l < 4; ++l)
                vf[l] = *(const float4*)&Vs[(kc * 4 + l) * 64 + tx * 4];
#pragma unroll
            for (int i = 0; i < 4; ++i) {
                Oa[i][0] += pf[i].x * vf[0].x + pf[i].y * vf[1].x +
                            pf[i].z * vf[2].x + pf[i].w * vf[3].x;
                Oa[i][1] += pf[i].x * vf[0].y + pf[i].y * vf[1].y +
                            pf[i].z * vf[2].y + pf[i].w * vf[3].y;
                Oa[i][2] += pf[i].x * vf[0].z + pf[i].y * vf[1].z +
                            pf[i].z * vf[2].z + pf[i].w * vf[3].z;
                Oa[i][3] += pf[i].x * vf[0].w + pf[i].y * vf[1].w +
                            pf[i].z * vf[2].w + pf[i].w * vf[3].w;
            }
        }
    }

#pragma unroll
    for (int i = 0; i < 4; ++i) {
        float inv = 1.0f / lrow[i];
        int s = qb * 64 + ty * 4 + i;
        size_t idx = ((size_t)(b * S_ + s) * H_ + h) * DK_ + tx * 4;
        *(float4*)(g_O + idx) = make_float4(Oa[i][0] * inv, Oa[i][1] * inv,
                                            Oa[i][2] * inv, Oa[i][3] * inv);
    }
}

// ---------------------------------------------------------------------------
// Launch
// ---------------------------------------------------------------------------
extern "C" void kernel_launch(void* const* d_in, const int* in_sizes, int n_in,
                              void* d_out, int out_size) {
    const float* x   = (const float*)d_in[0];
    const int*   pos = (const int*)d_in[1];
    const float* wq  = (const float*)d_in[2];
    const float* wk  = (const float*)d_in[3];
    const float* wv  = (const float*)d_in[4];
    const float* wo  = (const float*)d_in[5];
    float* out = (float*)d_out;
    (void)in_sizes; (void)n_in; (void)out_size;

    cudaFuncSetAttribute((const void*)mma_gemm_kernel<1, 0, 0, 0>,
                         cudaFuncAttributeMaxDynamicSharedMemorySize, GEMM_SMEM);
    cudaFuncSetAttribute((const void*)mma_gemm_kernel<1, 1, 0, 1>,
                         cudaFuncAttributeMaxDynamicSharedMemorySize, GEMM_SMEM);
    cudaFuncSetAttribute((const void*)mma_gemm_kernel<2, 2, 0, 2>,
                         cudaFuncAttributeMaxDynamicSharedMemorySize, GEMM_SMEM);
    cudaFuncSetAttribute((const void*)mma_gemm_kernel<0, 3, 1, 3>,
                         cudaFuncAttributeMaxDynamicSharedMemorySize, GEMM_SMEM);

    // 1. RoPE tables
    rope_table_kernel<<<(S_ * 32 + 255) / 256, 256>>>(pos);

    // 2. bf16 hi/lo splits of x and weights
    {
        int n4x = (M_ * D_) / 4, n4w = (D_ * D_) / 4;
        convert_split_kernel<0><<<(n4x + 255) / 256, 256>>>(x, n4x);
        convert_split_kernel<1><<<(n4w + 255) / 256, 256>>>(wq, n4w);
        convert_split_kernel<2><<<(n4w + 255) / 256, 256>>>(wk, n4w);
        convert_split_kernel<3><<<(n4w + 255) / 256, 256>>>(wv, n4w);
        convert_split_kernel<4><<<(n4w + 255) / 256, 256>>>(wo, n4w);
    }

    // 3. QKV projections on tensor cores (RoPE fused into epilogue)
    dim3 ggrid(D_ / 128, M_ / 128);
    mma_gemm_kernel<1, 0, 0, 0><<<ggrid, 256, GEMM_SMEM>>>(nullptr);
    mma_gemm_kernel<1, 1, 0, 1><<<ggrid, 256, GEMM_SMEM>>>(nullptr);
    mma_gemm_kernel<2, 2, 0, 2><<<ggrid, 256, GEMM_SMEM>>>(nullptr);

    // 4. Causal flash attention
    attn_kernel<<<dim3(S_ / 64, B_ * H_), 256>>>();

    // 5. Split O, output projection on tensor cores -> d_out
    {
        int n4o = (M_ * D_) / 4;
        convert_split_kernel<5><<<(n4o + 255) / 256, 256>>>(nullptr, n4o);
    }
    mma_gemm_kernel<0, 3, 1, 3><<<ggrid, 256, GEMM_SMEM>>>(out);
}

// round 6
// speedup vs baseline: 2.8774x; 1.8513x over previous
#include <cuda_runtime.h>
#include <cuda_bf16.h>
#include <math.h>
#include <stdint.h>

#define B_  4
#define S_  2048
#define D_  1024
#define H_  16
#define DK_ 64
#define M_  (B_ * S_)

// ---------------------------------------------------------------------------
// Device-global scratch (no allocations allowed)
// ---------------------------------------------------------------------------
__device__ float g_cos[S_ * 32];
__device__ float g_sin[S_ * 32];

// bf16 hi/lo split operands
__device__ __nv_bfloat16 g_xhi[(size_t)M_ * D_];
__device__ __nv_bfloat16 g_xlo[(size_t)M_ * D_];
__device__ __nv_bfloat16 g_whi[4][(size_t)D_ * D_];   // q,k,v,o
__device__ __nv_bfloat16 g_wlo[4][(size_t)D_ * D_];
__device__ __nv_bfloat16 g_ohi[(size_t)M_ * D_];
__device__ __nv_bfloat16 g_olo[(size_t)M_ * D_];

// Q/K/V in [b,h,s,dk] bf16 hi/lo (Q pre-scaled by 1/8)
__device__ __nv_bfloat16 g_Qhi[(size_t)B_ * H_ * S_ * DK_];
__device__ __nv_bfloat16 g_Qlo[(size_t)B_ * H_ * S_ * DK_];
__device__ __nv_bfloat16 g_Khi[(size_t)B_ * H_ * S_ * DK_];
__device__ __nv_bfloat16 g_Klo[(size_t)B_ * H_ * S_ * DK_];
__device__ __nv_bfloat16 g_Vhi[(size_t)B_ * H_ * S_ * DK_];
__device__ __nv_bfloat16 g_Vlo[(size_t)B_ * H_ * S_ * DK_];

// ---------------------------------------------------------------------------
// Warp-level tensor core helpers (sm_80+ PTX — assembles for plain sm_103)
// ---------------------------------------------------------------------------
__device__ __forceinline__ uint32_t smem_u32(const void* p) {
    uint32_t a;
    asm("{ .reg .u64 t; cvta.to.shared.u64 t, %1; cvt.u32.u64 %0, t; }"
        : "=r"(a) : "l"(p));
    return a;
}
__device__ __forceinline__ void ldsm_x4(uint32_t* r, uint32_t addr) {
    asm volatile("ldmatrix.sync.aligned.m8n8.x4.shared.b16 {%0,%1,%2,%3}, [%4];"
                 : "=r"(r[0]), "=r"(r[1]), "=r"(r[2]), "=r"(r[3]) : "r"(addr));
}
__device__ __forceinline__ void ldsm_x4_t(uint32_t* r, uint32_t addr) {
    asm volatile("ldmatrix.sync.aligned.m8n8.x4.trans.shared.b16 {%0,%1,%2,%3}, [%4];"
                 : "=r"(r[0]), "=r"(r[1]), "=r"(r[2]), "=r"(r[3]) : "r"(addr));
}
__device__ __forceinline__ void mma_bf16(float* d, const uint32_t* a,
                                         const uint32_t* b) {
    asm volatile(
        "mma.sync.aligned.m16n8k16.row.col.f32.bf16.bf16.f32 "
        "{%0,%1,%2,%3}, {%4,%5,%6,%7}, {%8,%9}, {%0,%1,%2,%3};"
        : "+f"(d[0]), "+f"(d[1]), "+f"(d[2]), "+f"(d[3])
        : "r"(a[0]), "r"(a[1]), "r"(a[2]), "r"(a[3]), "r"(b[0]), "r"(b[1]));
}
__device__ __forceinline__ uint32_t pack_bf16x2(float lo, float hi) {
    __nv_bfloat162 v = __halves2bfloat162(__float2bfloat16_rn(lo),
                                          __float2bfloat16_rn(hi));
    return *(uint32_t*)&v;
}

// ---------------------------------------------------------------------------
// RoPE table
// ---------------------------------------------------------------------------
__global__ void rope_table_kernel(const int* __restrict__ pos) {
    int idx = blockIdx.x * blockDim.x + threadIdx.x;
    if (idx >= S_ * 32) return;
    int s = idx >> 5;
    int p = idx & 31;
    float inv_freq = (float)pow(10000.0, -((double)(2 * p)) / 64.0);
    float ang = (float)pos[s] * inv_freq;
    g_cos[idx] = (float)cos((double)ang);
    g_sin[idx] = (float)sin((double)ang);
}

// ---------------------------------------------------------------------------
// fp32 -> bf16 hi/lo split. IDX: 0=x, 1..4=w[q,k,v,o]
// ---------------------------------------------------------------------------
template <int IDX>
__global__ void convert_split_kernel(const float* __restrict__ src, int n4) {
    int i = blockIdx.x * blockDim.x + threadIdx.x;
    if (i >= n4) return;
    __nv_bfloat16 *hi, *lo;
    if (IDX == 0) { hi = g_xhi; lo = g_xlo; }
    else          { hi = g_whi[IDX - 1]; lo = g_wlo[IDX - 1]; }

    float4 v = ((const float4*)src)[i];
    __nv_bfloat16 h0 = __float2bfloat16_rn(v.x);
    __nv_bfloat16 h1 = __float2bfloat16_rn(v.y);
    __nv_bfloat16 h2 = __float2bfloat16_rn(v.z);
    __nv_bfloat16 h3 = __float2bfloat16_rn(v.w);
    __nv_bfloat16 l0 = __float2bfloat16_rn(v.x - __bfloat162float(h0));
    __nv_bfloat16 l1 = __float2bfloat16_rn(v.y - __bfloat162float(h1));
    __nv_bfloat16 l2 = __float2bfloat16_rn(v.z - __bfloat162float(h2));
    __nv_bfloat16 l3 = __float2bfloat16_rn(v.w - __bfloat162float(h3));
    ((__nv_bfloat162*)hi)[2 * i]     = __halves2bfloat162(h0, h1);
    ((__nv_bfloat162*)hi)[2 * i + 1] = __halves2bfloat162(h2, h3);
    ((__nv_bfloat162*)lo)[2 * i]     = __halves2bfloat162(l0, l1);
    ((__nv_bfloat162*)lo)[2 * i + 1] = __halves2bfloat162(l2, l3);
}

// ---------------------------------------------------------------------------
// mma.sync bf16x3 GEMM: C[M,N] = A[M,1024] * W[N,1024]^T.
// CTA tile 128x128, BK=64, 8 warps (4x2), warp tile 32x64.
// MODE 0: fp32 row-major store to Cout
// MODE 1: RoPE + bf16 hi/lo split + scatter to Q (scaled 1/8) or K
// MODE 2: bf16 hi/lo split + scatter to V
// DST (MODE1/2): 0=Q, 1=K, 2=V. SRC: 0 -> x split, 1 -> O split.
// ---------------------------------------------------------------------------
#define T_STRIDE 144
#define T_BYTES  (128 * T_STRIDE)
#define GEMM_SMEM (4 * T_BYTES)

template <int MODE, int DST, int SRC, int WSEL>
__global__ void __launch_bounds__(256) mma_gemm_kernel(float* __restrict__ Cout) {
    extern __shared__ char sm[];
    const int tid  = threadIdx.x;
    const int w    = tid >> 5;
    const int lane = tid & 31;
    const int wm   = w >> 1;
    const int wn   = w & 1;
    const int n0   = blockIdx.x * 128;
    const int m0   = blockIdx.y * 128;

    const uint32_t sbase = smem_u32(sm);
    const uint32_t oA[2] = { 0u, (uint32_t)T_BYTES };
    const uint32_t oB[2] = { (uint32_t)(2 * T_BYTES), (uint32_t)(3 * T_BYTES) };

    const __nv_bfloat16* srcA[2] = {
        ((SRC == 0) ? g_xhi : g_ohi) + (size_t)m0 * D_,
        ((SRC == 0) ? g_xlo : g_olo) + (size_t)m0 * D_ };
    const __nv_bfloat16* srcB[2] = {
        g_whi[WSEL] + (size_t)n0 * D_,
        g_wlo[WSEL] + (size_t)n0 * D_ };

    float d[2][8][4];
#pragma unroll
    for (int i = 0; i < 2; ++i)
#pragma unroll
        for (int j = 0; j < 8; ++j)
#pragma unroll
            for (int q = 0; q < 4; ++q) d[i][j][q] = 0.f;

    for (int kt = 0; kt < 16; ++kt) {
        __syncthreads();
#pragma unroll
        for (int t = 0; t < 4; ++t) {
            const __nv_bfloat16* src = (t < 2) ? srcA[t] : srcB[t - 2];
            uint32_t dstoff = (t < 2) ? oA[t] : oB[t - 2];
            char* dst = sm + dstoff;
#pragma unroll
            for (int u = 0; u < 4; ++u) {
                int f = tid + u * 256;
                int r = f >> 3;
                int c = f & 7;
                uint4 v = *(const uint4*)(src + (size_t)r * D_ + kt * 64 + c * 8);
                *(uint4*)(dst + r * T_STRIDE + c * 16) = v;
            }
        }
        __syncthreads();

#pragma unroll
        for (int ks = 0; ks < 4; ++ks) {
            const int k0 = ks * 16;
            uint32_t ah[2][4], al[2][4];
            {
                int arow = wm * 32 + (lane & 15);
                int acol = 2 * k0 + (lane >> 4) * 16;
#pragma unroll
                for (int i = 0; i < 2; ++i) {
                    uint32_t off = (uint32_t)((arow + i * 16) * T_STRIDE + acol);
                    ldsm_x4(ah[i], sbase + oA[0] + off);
                    ldsm_x4(al[i], sbase + oA[1] + off);
                }
            }
            uint32_t bh[8][2], bl[8][2];
            {
                int brow_l = (lane & 7) + ((lane >> 4) & 1) * 8;
                int bcol   = 2 * k0 + ((lane >> 3) & 1) * 16;
#pragma unroll
                for (int g = 0; g < 4; ++g) {
                    uint32_t off = (uint32_t)((wn * 64 + g * 16 + brow_l) * T_STRIDE + bcol);
                    uint32_t r4[4];
                    ldsm_x4(r4, sbase + oB[0] + off);
                    bh[2 * g][0] = r4[0]; bh[2 * g][1] = r4[1];
                    bh[2 * g + 1][0] = r4[2]; bh[2 * g + 1][1] = r4[3];
                    ldsm_x4(r4, sbase + oB[1] + off);
                    bl[2 * g][0] = r4[0]; bl[2 * g][1] = r4[1];
                    bl[2 * g + 1][0] = r4[2]; bl[2 * g + 1][1] = r4[3];
                }
            }
#pragma unroll
            for (int i = 0; i < 2; ++i)
#pragma unroll
                for (int j = 0; j < 8; ++j) {
                    mma_bf16(d[i][j], ah[i], bh[j]);
                    mma_bf16(d[i][j], al[i], bh[j]);
                    mma_bf16(d[i][j], ah[i], bl[j]);
                }
        }
    }

    // Epilogue
#pragma unroll
    for (int i = 0; i < 2; ++i) {
        int mrow = m0 + wm * 32 + i * 16 + (lane >> 2);
#pragma unroll
        for (int half = 0; half < 2; ++half) {
            int m = mrow + half * 8;
            int b = m >> 11;
            int s = m & (S_ - 1);
#pragma unroll
            for (int j = 0; j < 8; ++j) {
                int n = n0 + wn * 64 + j * 8 + 2 * (lane & 3);
                float x0 = d[i][j][2 * half];
                float x1 = d[i][j][2 * half + 1];
                if (MODE == 0) {
                    *(float2*)(Cout + (size_t)m * D_ + n) = make_float2(x0, x1);
                } else {
                    int h = n >> 6;
                    int dk = n & 63;
                    float y0, y1;
                    if (MODE == 1) {
                        int p = dk >> 1;
                        float c = g_cos[s * 32 + p];
                        float sn = g_sin[s * 32 + p];
                        y0 = c * x0 - sn * x1;
                        y1 = sn * x0 + c * x1;
                    } else {
                        y0 = x0; y1 = x1;
                    }
                    if (DST == 0) { y0 *= 0.125f; y1 *= 0.125f; }   // fold 1/sqrt(dk)
                    __nv_bfloat16 h0 = __float2bfloat16_rn(y0);
                    __nv_bfloat16 h1 = __float2bfloat16_rn(y1);
                    __nv_bfloat16 l0 = __float2bfloat16_rn(y0 - __bfloat162float(h0));
                    __nv_bfloat16 l1 = __float2bfloat16_rn(y1 - __bfloat162float(h1));
                    size_t idx = (((size_t)(b * H_ + h) * S_ + s) * DK_ + dk);
                    __nv_bfloat16 *Chi, *Clo;
                    if (DST == 0)      { Chi = g_Qhi; Clo = g_Qlo; }
                    else if (DST == 1) { Chi = g_Khi; Clo = g_Klo; }
                    else               { Chi = g_Vhi; Clo = g_Vlo; }
                    *(__nv_bfloat162*)(Chi + idx) = __halves2bfloat162(h0, h1);
                    *(__nv_bfloat162*)(Clo + idx) = __halves2bfloat162(l0, l1);
                }
            }
        }
    }
}

// ---------------------------------------------------------------------------
// Tensor-core flash attention (causal, bf16x3).
// CTA = 128 queries of one (b,h); 8 warps, each m16 x full 64-dk.
// Key tiles of 64. QK^T via ldmatrix + mma; P stays in registers and feeds
// PV directly (QK D-frag == PV A-frag layout). Output -> g_ohi/g_olo.
// ---------------------------------------------------------------------------
#define AT_STRIDE 72          // bf16 per smem row (144 B)

__global__ void __launch_bounds__(256) attn_mma_kernel() {
    __shared__ __align__(16) __nv_bfloat16 sK[2][64 * AT_STRIDE];   // hi, lo
    __shared__ __align__(16) __nv_bfloat16 sV[2][64 * AT_STRIDE];

    const int qb = gridDim.x - 1 - blockIdx.x;     // heavy first
    const int bh = blockIdx.y;
    const int tid = threadIdx.x;
    const int w = tid >> 5;
    const int lane = tid & 31;
    const int q0w = qb * 128 + w * 16;
    const size_t hb = (size_t)bh * S_ * DK_;

    const uint32_t sKhi = smem_u32(sK[0]), sKlo = smem_u32(sK[1]);
    const uint32_t sVhi = smem_u32(sV[0]), sVlo = smem_u32(sV[1]);

    // Q fragments (pre-scaled by 1/8 in the GEMM epilogue)
    uint32_t qh[4][4], ql[4][4];
    {
        const int r0 = q0w + (lane >> 2);
        const int c2 = (lane & 3) * 2;
        const __nv_bfloat16* Qh = g_Qhi + hb;
        const __nv_bfloat16* Ql = g_Qlo + hb;
#pragma unroll
        for (int t = 0; t < 4; ++t) {
            qh[t][0] = *(const uint32_t*)(Qh + (size_t)r0 * 64 + t * 16 + c2);
            qh[t][1] = *(const uint32_t*)(Qh + (size_t)(r0 + 8) * 64 + t * 16 + c2);
            qh[t][2] = *(const uint32_t*)(Qh + (size_t)r0 * 64 + t * 16 + 8 + c2);
            qh[t][3] = *(const uint32_t*)(Qh + (size_t)(r0 + 8) * 64 + t * 16 + 8 + c2);
            ql[t][0] = *(const uint32_t*)(Ql + (size_t)r0 * 64 + t * 16 + c2);
            ql[t][1] = *(const uint32_t*)(Ql + (size_t)(r0 + 8) * 64 + t * 16 + c2);
            ql[t][2] = *(const uint32_t*)(Ql + (size_t)r0 * 64 + t * 16 + 8 + c2);
            ql[t][3] = *(const uint32_t*)(Ql + (size_t)(r0 + 8) * 64 + t * 16 + 8 + c2);
        }
    }

    float o[8][4];
#pragma unroll
    for (int j = 0; j < 8; ++j)
#pragma unroll
        for (int q = 0; q < 4; ++q) o[j][q] = 0.f;
    float m0 = -3.0e38f, m1 = -3.0e38f, l0 = 0.f, l1 = 0.f;

    const int nkt = 2 * qb + 2;
    for (int kt = 0; kt < nkt; ++kt) {
        const int k0 = kt * 64;
        __syncthreads();
        {
            const __nv_bfloat16* srcs[4] = {
                g_Khi + hb + (size_t)k0 * 64, g_Klo + hb + (size_t)k0 * 64,
                g_Vhi + hb + (size_t)k0 * 64, g_Vlo + hb + (size_t)k0 * 64 };
            __nv_bfloat16* dsts[4] = { sK[0], sK[1], sV[0], sV[1] };
#pragma unroll
            for (int t4 = 0; t4 < 4; ++t4) {
#pragma unroll
                for (int u = 0; u < 2; ++u) {
                    int f = tid + u * 256;
                    int r = f >> 3;
                    int c = f & 7;
                    uint4 v = *(const uint4*)(srcs[t4] + (size_t)r * 64 + c * 8);
                    *(uint4*)((char*)dsts[t4] + r * 144 + c * 16) = v;
                }
            }
        }
        __syncthreads();

        if (q0w + 15 < k0) continue;     // warp fully masked for this tile

        // ---- S = Q * K^T ----
        float s[8][4];
#pragma unroll
        for (int j = 0; j < 8; ++j)
#pragma unroll
            for (int q = 0; q < 4; ++q) s[j][q] = 0.f;

#pragma unroll
        for (int t = 0; t < 4; ++t) {
            uint32_t kh[8][2], kl[8][2];
            int brow = (lane & 7) + ((lane >> 4) & 1) * 8;
            int bcol = t * 32 + ((lane >> 3) & 1) * 16;   // bytes
#pragma unroll
            for (int g = 0; g < 4; ++g) {
                uint32_t off = (uint32_t)((g * 16 + brow) * 144 + bcol);
                uint32_t r4[4];
                ldsm_x4(r4, sKhi + off);
                kh[2 * g][0] = r4[0]; kh[2 * g][1] = r4[1];
                kh[2 * g + 1][0] = r4[2]; kh[2 * g + 1][1] = r4[3];
                ldsm_x4(r4, sKlo + off);
                kl[2 * g][0] = r4[0]; kl[2 * g][1] = r4[1];
                kl[2 * g + 1][0] = r4[2]; kl[2 * g + 1][1] = r4[3];
            }
#pragma unroll
            for (int j = 0; j < 8; ++j) {
                mma_bf16(s[j], qh[t], kh[j]);
                mma_bf16(s[j], ql[t], kh[j]);
                mma_bf16(s[j], qh[t], kl[j]);
            }
        }

        // ---- causal mask ----
        const int r0 = q0w + (lane >> 2);
        if (k0 + 63 > q0w) {
#pragma unroll
            for (int j = 0; j < 8; ++j) {
                int col = k0 + 8 * j + 2 * (lane & 3);
                if (col > r0)         s[j][0] = -3.0e38f;
                if (col + 1 > r0)     s[j][1] = -3.0e38f;
                if (col > r0 + 8)     s[j][2] = -3.0e38f;
                if (col + 1 > r0 + 8) s[j][3] = -3.0e38f;
            }
        }

        // ---- online softmax ----
        float mx0 = -3.0e38f, mx1 = -3.0e38f;
#pragma unroll
        for (int j = 0; j < 8; ++j) {
            mx0 = fmaxf(mx0, fmaxf(s[j][0], s[j][1]));
            mx1 = fmaxf(mx1, fmaxf(s[j][2], s[j][3]));
        }
        mx0 = fmaxf(mx0, __shfl_xor_sync(0xffffffffu, mx0, 1));
        mx0 = fmaxf(mx0, __shfl_xor_sync(0xffffffffu, mx0, 2));
        mx1 = fmaxf(mx1, __shfl_xor_sync(0xffffffffu, mx1, 1));
        mx1 = fmaxf(mx1, __shfl_xor_sync(0xffffffffu, mx1, 2));
        float mn0 = fmaxf(m0, mx0), mn1 = fmaxf(m1, mx1);
        float a0 = __expf(m0 - mn0), a1 = __expf(m1 - mn1);

        uint32_t Ph[8][2], Pl[8][2];
        float sum0 = 0.f, sum1 = 0.f;
#pragma unroll
        for (int j = 0; j < 8; ++j) {
            float p0 = __expf(s[j][0] - mn0);
            float p1 = __expf(s[j][1] - mn0);
            float p2 = __expf(s[j][2] - mn1);
            float p3 = __expf(s[j][3] - mn1);
            sum0 += p0 + p1;
            sum1 += p2 + p3;
            __nv_bfloat16 h0 = __float2bfloat16_rn(p0), h1 = __float2bfloat16_rn(p1);
            __nv_bfloat16 h2 = __float2bfloat16_rn(p2), h3 = __float2bfloat16_rn(p3);
            __nv_bfloat162 vh01 = __halves2bfloat162(h0, h1);
            __nv_bfloat162 vh23 = __halves2bfloat162(h2, h3);
            Ph[j][0] = *(uint32_t*)&vh01;
            Ph[j][1] = *(uint32_t*)&vh23;
            Pl[j][0] = pack_bf16x2(p0 - __bfloat162float(h0), p1 - __bfloat162float(h1));
            Pl[j][1] = pack_bf16x2(p2 - __bfloat162float(h2), p3 - __bfloat162float(h3));
        }
        sum0 += __shfl_xor_sync(0xffffffffu, sum0, 1);
        sum0 += __shfl_xor_sync(0xffffffffu, sum0, 2);
        sum1 += __shfl_xor_sync(0xffffffffu, sum1, 1);
        sum1 += __shfl_xor_sync(0xffffffffu, sum1, 2);
        l0 = l0 * a0 + sum0;
        l1 = l1 * a1 + sum1;
        m0 = mn0; m1 = mn1;
#pragma unroll
        for (int j = 0; j < 8; ++j) {
            o[j][0] *= a0; o[j][1] *= a0; o[j][2] *= a1; o[j][3] *= a1;
        }

        // ---- O += P * V ----
#pragma unroll
        for (int t = 0; t < 4; ++t) {
            uint32_t ap[4] = { Ph[2 * t][0], Ph[2 * t][1],
                               Ph[2 * t + 1][0], Ph[2 * t + 1][1] };
            uint32_t alr[4] = { Pl[2 * t][0], Pl[2 * t][1],
                                Pl[2 * t + 1][0], Pl[2 * t + 1][1] };
            uint32_t vh[8][2], vl[8][2];
            int vrow = t * 16 + (lane & 15);
#pragma unroll
            for (int g = 0; g < 4; ++g) {
                uint32_t off = (uint32_t)(vrow * 144 + (g * 16 + (lane >> 4) * 8) * 2);
                uint32_t r4[4];
                ldsm_x4_t(r4, sVhi + off);
                vh[2 * g][0] = r4[0]; vh[2 * g][1] = r4[1];
                vh[2 * g + 1][0] = r4[2]; vh[2 * g + 1][1] = r4[3];
                ldsm_x4_t(r4, sVlo + off);
                vl[2 * g][0] = r4[0]; vl[2 * g][1] = r4[1];
                vl[2 * g + 1][0] = r4[2]; vl[2 * g + 1][1] = r4[3];
            }
#pragma unroll
            for (int j = 0; j < 8; ++j) {
                mma_bf16(o[j], ap, vh[j]);
                mma_bf16(o[j], alr, vh[j]);
                mma_bf16(o[j], ap, vl[j]);
            }
        }
    }

    // ---- epilogue: normalize, split hi/lo, write [b,s,h*dk] ----
    const float inv0 = 1.0f / l0, inv1 = 1.0f / l1;
    const int b = bh >> 4, h = bh & 15;
    const int s0 = q0w + (lane >> 2);
    const int c2 = 2 * (lane & 3);
#pragma unroll
    for (int j = 0; j < 8; ++j) {
        int dk = 8 * j + c2;
        {
            float y0 = o[j][0] * inv0, y1 = o[j][1] * inv0;
            __nv_bfloat16 h0 = __float2bfloat16_rn(y0), h1 = __float2bfloat16_rn(y1);
            size_t idx = ((size_t)(b * S_) + s0) * D_ + h * 64 + dk;
            *(__nv_bfloat162*)(g_ohi + idx) = __halves2bfloat162(h0, h1);
            *(uint32_t*)(g_olo + idx) =
                pack_bf16x2(y0 - __bfloat162float(h0), y1 - __bfloat162float(h1));
        }
        {
            float y0 = o[j][2] * inv1, y1 = o[j][3] * inv1;
            __nv_bfloat16 h0 = __float2bfloat16_rn(y0), h1 = __float2bfloat16_rn(y1);
            size_t idx = ((size_t)(b * S_) + s0 + 8) * D_ + h * 64 + dk;
            *(__nv_bfloat162*)(g_ohi + idx) = __halves2bfloat162(h0, h1);
            *(uint32_t*)(g_olo + idx) =
                pack_bf16x2(y0 - __bfloat162float(h0), y1 - __bfloat162float(h1));
        }
    }
}

// ---------------------------------------------------------------------------
// Launch
// ---------------------------------------------------------------------------
extern "C" void kernel_launch(void* const* d_in, const int* in_sizes, int n_in,
                              void* d_out, int out_size) {
    const float* x   = (const float*)d_in[0];
    const int*   pos = (const int*)d_in[1];
    const float* wq  = (const float*)d_in[2];
    const float* wk  = (const float*)d_in[3];
    const float* wv  = (const float*)d_in[4];
    const float* wo  = (const float*)d_in[5];
    float* out = (float*)d_out;
    (void)in_sizes; (void)n_in; (void)out_size;

    cudaFuncSetAttribute((const void*)mma_gemm_kernel<1, 0, 0, 0>,
                         cudaFuncAttributeMaxDynamicSharedMemorySize, GEMM_SMEM);
    cudaFuncSetAttribute((const void*)mma_gemm_kernel<1, 1, 0, 1>,
                         cudaFuncAttributeMaxDynamicSharedMemorySize, GEMM_SMEM);
    cudaFuncSetAttribute((const void*)mma_gemm_kernel<2, 2, 0, 2>,
                         cudaFuncAttributeMaxDynamicSharedMemorySize, GEMM_SMEM);
    cudaFuncSetAttribute((const void*)mma_gemm_kernel<0, 3, 1, 3>,
                         cudaFuncAttributeMaxDynamicSharedMemorySize, GEMM_SMEM);

    // 1. RoPE tables
    rope_table_kernel<<<(S_ * 32 + 255) / 256, 256>>>(pos);

    // 2. bf16 hi/lo splits of x and weights
    {
        int n4x = (M_ * D_) / 4, n4w = (D_ * D_) / 4;
        convert_split_kernel<0><<<(n4x + 255) / 256, 256>>>(x, n4x);
        convert_split_kernel<1><<<(n4w + 255) / 256, 256>>>(wq, n4w);
        convert_split_kernel<2><<<(n4w + 255) / 256, 256>>>(wk, n4w);
        convert_split_kernel<3><<<(n4w + 255) / 256, 256>>>(wv, n4w);
        convert_split_kernel<4><<<(n4w + 255) / 256, 256>>>(wo, n4w);
    }

    // 3. QKV projections on tensor cores (RoPE + bf16 split fused)
    dim3 ggrid(D_ / 128, M_ / 128);
    mma_gemm_kernel<1, 0, 0, 0><<<ggrid, 256, GEMM_SMEM>>>(nullptr);
    mma_gemm_kernel<1, 1, 0, 1><<<ggrid, 256, GEMM_SMEM>>>(nullptr);
    mma_gemm_kernel<2, 2, 0, 2><<<ggrid, 256, GEMM_SMEM>>>(nullptr);

    // 4. Tensor-core causal flash attention -> g_ohi/g_olo
    attn_mma_kernel<<<dim3(S_ / 128, B_ * H_), 256>>>();

    // 5. Output projection on tensor cores -> d_out
    mma_gemm_kernel<0, 3, 1, 3><<<ggrid, 256, GEMM_SMEM>>>(out);
}